// round 5
// baseline (speedup 1.0000x reference)
#include <cuda_runtime.h>
#include <cuda_fp16.h>

#define N_NODES 100000
#define N_EDGES 1600000
#define C_IN    64
#define C_HID   64
#define C_OUT   32

#define SCAN_BLK 512
#define N_SCAN_BLOCKS ((N_NODES + SCAN_BLK - 1) / SCAN_BLK)   // 196

#define FIXP 16777216.0f   // 2^24 fixed-point scale for ew accumulation

// ----- scratch (device globals; no runtime allocation) ----------------------
__device__ unsigned long long g_pack[N_NODES];   // cnt<<40 | sum(ew)*2^24
__device__ float g_deg[N_NODES];                 // dinv
__device__ int   g_cnt[N_NODES];
__device__ int   g_rs [N_NODES];                 // CSR row start
__device__ int   g_cur[N_NODES];                 // fill cursor

// decoupled-lookback scan state
__device__ int            g_tick;
__device__ volatile int   g_flag[N_SCAN_BLOCKS]; // 0=none 1=aggregate 2=prefix
__device__ volatile int   g_aggv[N_SCAN_BLOCKS];
__device__ volatile int   g_pref[N_SCAN_BLOCKS];

struct EdgeRec { int src; float w; };            // w = dinv[src] * ew
__device__ EdgeRec g_csr[N_EDGES];

__device__ __align__(16) __half g_h1h[N_NODES * C_HID];  // x @ W1   (fp16)
__device__ __align__(16) float  g_o1 [N_NODES * C_HID];  // relu(layer-1 out)
__device__ __align__(16) __half g_h2h[N_NODES * C_OUT];  // o1 @ W2  (fp16)

// ---------------------------------------------------------------------------
__global__ void k_init() {
    int i = blockIdx.x * blockDim.x + threadIdx.x;
    if (i < N_NODES) g_pack[i] = 0ull;
    if (i < N_SCAN_BLOCKS) g_flag[i] = 0;
    if (i == 0) g_tick = 0;
}

// one 64-bit atomic per edge; 2 edges per thread (vectorized loads)
__global__ void k_deg(const int* __restrict__ ei, const float* __restrict__ ew) {
    int t = blockIdx.x * blockDim.x + threadIdx.x;
    if (t < N_EDGES / 2) {
        int2   d2 = ((const int2*)(ei + N_EDGES))[t];
        float2 w2 = ((const float2*)ew)[t];
        atomicAdd(&g_pack[d2.x],
                  (1ull << 40) | (unsigned long long)(w2.x * FIXP + 0.5f));
        atomicAdd(&g_pack[d2.y],
                  (1ull << 40) | (unsigned long long)(w2.y * FIXP + 0.5f));
    }
}

// single-pass scan: unpack cnt + dinv, exclusive scan -> g_rs/g_cur
__global__ void k_scan() {
    __shared__ int warp_sums[16];
    __shared__ int sh_bid, sh_exc;
    if (threadIdx.x == 0) sh_bid = atomicAdd(&g_tick, 1);
    __syncthreads();
    int bid = sh_bid;
    int i = bid * SCAN_BLK + threadIdx.x;

    int v = 0;
    if (i < N_NODES) {
        unsigned long long p = g_pack[i];
        v = (int)(p >> 40);
        g_cnt[i] = v;
        float deg = 1.0f + (float)(p & 0xFFFFFFFFFFull) * (1.0f / FIXP);
        g_deg[i] = rsqrtf(deg);
    }

    int lane = threadIdx.x & 31, wid = threadIdx.x >> 5;
    int inc = v;
    #pragma unroll
    for (int o = 1; o < 32; o <<= 1) {
        int t = __shfl_up_sync(0xffffffffu, inc, o);
        if (lane >= o) inc += t;
    }
    if (lane == 31) warp_sums[wid] = inc;
    __syncthreads();
    if (wid == 0) {
        int s = (lane < 16) ? warp_sums[lane] : 0;
        #pragma unroll
        for (int o = 1; o < 16; o <<= 1) {
            int t = __shfl_up_sync(0xffffffffu, s, o);
            if (lane >= o) s += t;
        }
        if (lane < 16) warp_sums[lane] = s;
    }
    __syncthreads();
    int incl = inc + ((wid > 0) ? warp_sums[wid - 1] : 0);
    int total = warp_sums[15];

    if (threadIdx.x == 0) {
        g_aggv[bid] = total;
        __threadfence();
        if (bid == 0) {
            g_pref[0] = total;
            __threadfence();
            g_flag[0] = 2;
            sh_exc = 0;
        } else {
            g_flag[bid] = 1;          // publish aggregate before lookback
            int exc = 0;
            int j = bid - 1;
            while (true) {
                int f;
                while ((f = g_flag[j]) == 0) {}
                if (f == 2) { exc += g_pref[j]; break; }
                exc += g_aggv[j];
                --j;
            }
            g_pref[bid] = exc + total;
            __threadfence();
            g_flag[bid] = 2;
            sh_exc = exc;
        }
    }
    __syncthreads();
    if (i < N_NODES) {
        int r = sh_exc + incl - v;    // exclusive
        g_rs[i] = r;
        g_cur[i] = r;
    }
}

// CSR fill: 2 edges per thread
__global__ void k_fill(const int* __restrict__ ei, const float* __restrict__ ew) {
    int t = blockIdx.x * blockDim.x + threadIdx.x;
    if (t < N_EDGES / 2) {
        int2   s2 = ((const int2*)ei)[t];
        int2   d2 = ((const int2*)(ei + N_EDGES))[t];
        float2 w2 = ((const float2*)ew)[t];
        int p0 = atomicAdd(&g_cur[d2.x], 1);
        EdgeRec e0; e0.src = s2.x; e0.w = __ldg(&g_deg[s2.x]) * w2.x;
        g_csr[p0] = e0;
        int p1 = atomicAdd(&g_cur[d2.y], 1);
        EdgeRec e1; e1.src = s2.y; e1.w = __ldg(&g_deg[s2.y]) * w2.y;
        g_csr[p1] = e1;
    }
}

// ---------------------------------------------------------------------------
// GEMM1: h1 = x @ W1 (fp16 out). W column in registers, xs via float4 smem.
__global__ void k_gemm1(const float* __restrict__ x, const float* __restrict__ W1) {
    __shared__ float4 xs[16][16];          // 16 rows x 64 floats
    int tx = threadIdx.x & 63;
    int ty = threadIdx.x >> 6;

    float4 w4[16];
    #pragma unroll
    for (int k4 = 0; k4 < 16; ++k4) {
        w4[k4].x = W1[(4 * k4 + 0) * 64 + tx];
        w4[k4].y = W1[(4 * k4 + 1) * 64 + tx];
        w4[k4].z = W1[(4 * k4 + 2) * 64 + tx];
        w4[k4].w = W1[(4 * k4 + 3) * 64 + tx];
    }

    int base = blockIdx.x * 64;
    for (int t = 0; t < 4; ++t) {
        int row0 = base + t * 16;
        __syncthreads();
        {
            int r = threadIdx.x >> 4, c = threadIdx.x & 15;
            if (row0 + r < N_NODES)
                xs[r][c] = ((const float4*)(x + (size_t)(row0 + r) * 64))[c];
        }
        __syncthreads();
        float acc[4] = {0.f, 0.f, 0.f, 0.f};
        #pragma unroll
        for (int k4 = 0; k4 < 16; ++k4) {
            float4 wv = w4[k4];
            #pragma unroll
            for (int r = 0; r < 4; ++r) {
                float4 xv = xs[ty * 4 + r][k4];
                acc[r] += xv.x * wv.x + xv.y * wv.y + xv.z * wv.z + xv.w * wv.w;
            }
        }
        #pragma unroll
        for (int r = 0; r < 4; ++r) {
            int row = row0 + ty * 4 + r;
            if (row < N_NODES)
                g_h1h[(size_t)row * 64 + tx] = __float2half_rn(acc[r]);
        }
    }
}

// Aggregation layer 1: one warp per dst; unroll x8 for L2 MLP.
__global__ void k_agg1(const float* __restrict__ b1) {
    int w = (blockIdx.x * blockDim.x + threadIdx.x) >> 5;
    int lane = threadIdx.x & 31;
    if (w >= N_NODES) return;
    int beg = g_rs[w];
    int n   = g_cnt[w];
    const __half2* h1v = (const __half2*)g_h1h;

    float a0 = 0.f, a1 = 0.f;
    int i = 0;
    for (; i + 7 < n; i += 8) {
        EdgeRec e0 = g_csr[beg + i + 0];
        EdgeRec e1 = g_csr[beg + i + 1];
        EdgeRec e2 = g_csr[beg + i + 2];
        EdgeRec e3 = g_csr[beg + i + 3];
        EdgeRec e4 = g_csr[beg + i + 4];
        EdgeRec e5 = g_csr[beg + i + 5];
        EdgeRec e6 = g_csr[beg + i + 6];
        EdgeRec e7 = g_csr[beg + i + 7];
        float2 f0 = __half22float2(__ldg(h1v + (size_t)e0.src * 32 + lane));
        float2 f1 = __half22float2(__ldg(h1v + (size_t)e1.src * 32 + lane));
        float2 f2 = __half22float2(__ldg(h1v + (size_t)e2.src * 32 + lane));
        float2 f3 = __half22float2(__ldg(h1v + (size_t)e3.src * 32 + lane));
        float2 f4 = __half22float2(__ldg(h1v + (size_t)e4.src * 32 + lane));
        float2 f5 = __half22float2(__ldg(h1v + (size_t)e5.src * 32 + lane));
        float2 f6 = __half22float2(__ldg(h1v + (size_t)e6.src * 32 + lane));
        float2 f7 = __half22float2(__ldg(h1v + (size_t)e7.src * 32 + lane));
        a0 += e0.w * f0.x + e1.w * f1.x + e2.w * f2.x + e3.w * f3.x
            + e4.w * f4.x + e5.w * f5.x + e6.w * f6.x + e7.w * f7.x;
        a1 += e0.w * f0.y + e1.w * f1.y + e2.w * f2.y + e3.w * f3.y
            + e4.w * f4.y + e5.w * f5.y + e6.w * f6.y + e7.w * f7.y;
    }
    for (; i < n; ++i) {
        EdgeRec er = g_csr[beg + i];
        float2 f = __half22float2(__ldg(h1v + (size_t)er.src * 32 + lane));
        a0 += er.w * f.x;
        a1 += er.w * f.y;
    }
    float di = g_deg[w];
    float2 hs = __half22float2(h1v[(size_t)w * 32 + lane]);
    float2 bb = ((const float2*)b1)[lane];
    a0 = di * a0 + di * di * hs.x + bb.x;
    a1 = di * a1 + di * di * hs.y + bb.y;
    ((float2*)g_o1)[(size_t)w * 32 + lane] =
        make_float2(fmaxf(a0, 0.f), fmaxf(a1, 0.f));
}

// GEMM2: h2 = o1 @ W2 (fp16 out). block 256 = 32 ch x 8 ty; 4 rows/thread.
__global__ void k_gemm2(const float* __restrict__ W2) {
    __shared__ float4 xs[32][16];          // 32 rows x 64 floats
    int tx = threadIdx.x & 31;
    int ty = threadIdx.x >> 5;

    float4 w4[16];
    #pragma unroll
    for (int k4 = 0; k4 < 16; ++k4) {
        w4[k4].x = W2[(4 * k4 + 0) * 32 + tx];
        w4[k4].y = W2[(4 * k4 + 1) * 32 + tx];
        w4[k4].z = W2[(4 * k4 + 2) * 32 + tx];
        w4[k4].w = W2[(4 * k4 + 3) * 32 + tx];
    }

    int base = blockIdx.x * 128;
    for (int t = 0; t < 4; ++t) {
        int row0 = base + t * 32;
        __syncthreads();
        {
            int idx = threadIdx.x;
            #pragma unroll
            for (int j = 0; j < 2; ++j, idx += 256) {
                int r = idx >> 4, c = idx & 15;
                if (row0 + r < N_NODES)
                    xs[r][c] = ((const float4*)(g_o1 + (size_t)(row0 + r) * 64))[c];
            }
        }
        __syncthreads();
        float acc[4] = {0.f, 0.f, 0.f, 0.f};
        #pragma unroll
        for (int k4 = 0; k4 < 16; ++k4) {
            float4 wv = w4[k4];
            #pragma unroll
            for (int r = 0; r < 4; ++r) {
                float4 xv = xs[ty * 4 + r][k4];
                acc[r] += xv.x * wv.x + xv.y * wv.y + xv.z * wv.z + xv.w * wv.w;
            }
        }
        #pragma unroll
        for (int r = 0; r < 4; ++r) {
            int row = row0 + ty * 4 + r;
            if (row < N_NODES)
                g_h2h[(size_t)row * 32 + tx] = __float2half_rn(acc[r]);
        }
    }
}

// Aggregation layer 2: warp per dst; half-warps interleave edges, unroll x4.
__global__ void k_agg2(const float* __restrict__ b2, float* __restrict__ out) {
    int w = (blockIdx.x * blockDim.x + threadIdx.x) >> 5;
    int lane = threadIdx.x & 31;
    if (w >= N_NODES) return;
    int half = lane >> 4;      // 0 or 1
    int c2   = lane & 15;      // half2 index within node
    int beg = g_rs[w];
    int n   = g_cnt[w];
    const __half2* h2v = (const __half2*)g_h2h;

    float a0 = 0.f, a1 = 0.f;
    int i = half;
    for (; i + 6 < n; i += 8) {       // this half handles i, i+2, i+4, i+6
        EdgeRec ea = g_csr[beg + i];
        EdgeRec eb = g_csr[beg + i + 2];
        EdgeRec ec = g_csr[beg + i + 4];
        EdgeRec ed = g_csr[beg + i + 6];
        float2 fa = __half22float2(__ldg(h2v + (size_t)ea.src * 16 + c2));
        float2 fb = __half22float2(__ldg(h2v + (size_t)eb.src * 16 + c2));
        float2 fc = __half22float2(__ldg(h2v + (size_t)ec.src * 16 + c2));
        float2 fd = __half22float2(__ldg(h2v + (size_t)ed.src * 16 + c2));
        a0 += ea.w * fa.x + eb.w * fb.x + ec.w * fc.x + ed.w * fd.x;
        a1 += ea.w * fa.y + eb.w * fb.y + ec.w * fc.y + ed.w * fd.y;
    }
    for (; i < n; i += 2) {
        EdgeRec er = g_csr[beg + i];
        float2 f = __half22float2(__ldg(h2v + (size_t)er.src * 16 + c2));
        a0 += er.w * f.x;
        a1 += er.w * f.y;
    }
    a0 += __shfl_xor_sync(0xffffffffu, a0, 16);
    a1 += __shfl_xor_sync(0xffffffffu, a1, 16);

    if (half == 0) {
        float di = g_deg[w];
        float2 hs = __half22float2(h2v[(size_t)w * 16 + c2]);
        float2 bb = ((const float2*)b2)[c2];
        float o0 = di * a0 + di * di * hs.x + bb.x;
        float o1v = di * a1 + di * di * hs.y + bb.y;
        ((float2*)out)[(size_t)w * 16 + c2] = make_float2(o0, o1v);
    }
}

// ---------------------------------------------------------------------------
extern "C" void kernel_launch(void* const* d_in, const int* in_sizes, int n_in,
                              void* d_out, int out_size) {
    const float* x  = (const float*)d_in[0];
    const int*   ei = (const int*)d_in[1];
    const float* ew = (const float*)d_in[2];
    const float* W1 = (const float*)d_in[3];
    const float* b1 = (const float*)d_in[4];
    const float* W2 = (const float*)d_in[5];
    const float* b2 = (const float*)d_in[6];
    float* out = (float*)d_out;

    k_init <<<(N_NODES + 255) / 256, 256>>>();
    k_deg  <<<(N_EDGES / 2 + 255) / 256, 256>>>(ei, ew);
    k_scan <<<N_SCAN_BLOCKS, SCAN_BLK>>>();
    k_fill <<<(N_EDGES / 2 + 255) / 256, 256>>>(ei, ew);

    k_gemm1<<<(N_NODES + 63) / 64, 256>>>(x, W1);
    k_agg1 <<<(N_NODES * 32 + 255) / 256, 256>>>(b1);
    k_gemm2<<<(N_NODES + 127) / 128, 256>>>(W2);
    k_agg2 <<<(N_NODES * 32 + 255) / 256, 256>>>(b2, out);
}

// round 6
// speedup vs baseline: 1.1044x; 1.1044x over previous
#include <cuda_runtime.h>
#include <cuda_fp16.h>

#define N_NODES 100000
#define N_EDGES 1600000
#define C_IN    64
#define C_HID   64
#define C_OUT   32

#define SCAN_BLK 512
#define N_SCAN_BLOCKS ((N_NODES + SCAN_BLK - 1) / SCAN_BLK)   // 196

#define FIXP 16777216.0f   // 2^24 fixed-point scale for ew accumulation

// ----- scratch (device globals; no runtime allocation) ----------------------
__device__ unsigned long long g_pack[N_NODES];   // cnt<<40 | sum(ew)*2^24
__device__ float g_deg[N_NODES];                 // dinv
__device__ int   g_cnt[N_NODES];
__device__ int   g_rs [N_NODES];                 // CSR row start
__device__ int   g_rank[N_EDGES];                // edge rank within dst bucket

// decoupled-lookback scan state: (value<<2)|flag, flag: 0 none, 1 agg, 2 prefix
__device__ int                         g_tick;
__device__ volatile unsigned long long g_state[N_SCAN_BLOCKS];

struct EdgeRec { int src; float w; };            // w = ew (dinv folded into h)
__device__ EdgeRec g_csr[N_EDGES];

__device__ __align__(16) __half g_h1h[N_NODES * C_HID];  // dinv * (x @ W1)  fp16
__device__ __align__(16) float  g_o1 [N_NODES * C_HID];  // relu(layer-1 out)
__device__ __align__(16) __half g_h2h[N_NODES * C_OUT];  // dinv * (o1 @ W2) fp16

// ---------------------------------------------------------------------------
__global__ void k_init() {
    int i = blockIdx.x * blockDim.x + threadIdx.x;
    if (i < N_NODES) g_pack[i] = 0ull;
    if (i < N_SCAN_BLOCKS) g_state[i] = 0ull;
    if (i == 0) g_tick = 0;
}

// one 64-bit atomic per edge; returned old count = rank within dst bucket
__global__ void k_deg(const int* __restrict__ ei, const float* __restrict__ ew) {
    int t = blockIdx.x * blockDim.x + threadIdx.x;
    if (t < N_EDGES / 2) {
        int2   d2 = ((const int2*)(ei + N_EDGES))[t];
        float2 w2 = ((const float2*)ew)[t];
        unsigned long long o0 = atomicAdd(&g_pack[d2.x],
            (1ull << 40) | (unsigned long long)(w2.x * FIXP + 0.5f));
        unsigned long long o1 = atomicAdd(&g_pack[d2.y],
            (1ull << 40) | (unsigned long long)(w2.y * FIXP + 0.5f));
        ((int2*)g_rank)[t] = make_int2((int)(o0 >> 40), (int)(o1 >> 40));
    }
}

// single-pass scan (warp-parallel decoupled lookback): cnt, dinv, g_rs
__global__ void k_scan() {
    __shared__ int warp_sums[16];
    __shared__ int sh_bid, sh_exc;
    if (threadIdx.x == 0) sh_bid = atomicAdd(&g_tick, 1);
    __syncthreads();
    int bid = sh_bid;
    int i = bid * SCAN_BLK + threadIdx.x;

    int v = 0;
    if (i < N_NODES) {
        unsigned long long p = g_pack[i];
        v = (int)(p >> 40);
        g_cnt[i] = v;
        float deg = 1.0f + (float)(p & 0xFFFFFFFFFFull) * (1.0f / FIXP);
        g_deg[i] = rsqrtf(deg);
    }

    int lane = threadIdx.x & 31, wid = threadIdx.x >> 5;
    int inc = v;
    #pragma unroll
    for (int o = 1; o < 32; o <<= 1) {
        int t = __shfl_up_sync(0xffffffffu, inc, o);
        if (lane >= o) inc += t;
    }
    if (lane == 31) warp_sums[wid] = inc;
    __syncthreads();
    if (wid == 0) {
        int s = (lane < 16) ? warp_sums[lane] : 0;
        #pragma unroll
        for (int o = 1; o < 16; o <<= 1) {
            int t = __shfl_up_sync(0xffffffffu, s, o);
            if (lane >= o) s += t;
        }
        if (lane < 16) warp_sums[lane] = s;
    }
    __syncthreads();
    int incl = inc + ((wid > 0) ? warp_sums[wid - 1] : 0);
    int total = warp_sums[15];

    // publish aggregate, then warp 0 does parallel lookback
    if (threadIdx.x == 0)
        g_state[bid] = ((unsigned long long)total << 2) | 1ull;

    if (wid == 0) {
        int exc = 0;
        if (bid > 0) {
            int j = bid - 1;
            while (true) {
                int jj = j - lane;
                unsigned long long s;
                do {
                    s = (jj >= 0) ? g_state[jj] : 2ull;   // jj<0: prefix of 0
                } while (__any_sync(0xffffffffu, (s & 3ull) == 0ull));
                unsigned pm = __ballot_sync(0xffffffffu, (s & 3ull) == 2ull);
                if (pm) {
                    int fp = __ffs(pm) - 1;               // nearest prefix
                    int val = (lane <= fp) ? (int)(s >> 2) : 0;
                    #pragma unroll
                    for (int o = 16; o; o >>= 1)
                        val += __shfl_xor_sync(0xffffffffu, val, o);
                    exc += val;
                    break;
                } else {
                    int val = (int)(s >> 2);              // all aggregates
                    #pragma unroll
                    for (int o = 16; o; o >>= 1)
                        val += __shfl_xor_sync(0xffffffffu, val, o);
                    exc += val;
                    j -= 32;
                }
            }
        }
        if (lane == 0) {
            g_state[bid] = ((unsigned long long)(exc + total) << 2) | 2ull;
            sh_exc = exc;
        }
    }
    __syncthreads();
    if (i < N_NODES) g_rs[i] = sh_exc + incl - v;          // exclusive
}

// CSR fill: NO atomics. slot = rs[dst] + rank[e]; w = ew only.
__global__ void k_fill(const int* __restrict__ ei, const float* __restrict__ ew) {
    int t = blockIdx.x * blockDim.x + threadIdx.x;
    if (t < N_EDGES / 2) {
        int2   s2 = ((const int2*)ei)[t];
        int2   d2 = ((const int2*)(ei + N_EDGES))[t];
        float2 w2 = ((const float2*)ew)[t];
        int2   r2 = ((const int2*)g_rank)[t];
        EdgeRec e0; e0.src = s2.x; e0.w = w2.x;
        g_csr[g_rs[d2.x] + r2.x] = e0;
        EdgeRec e1; e1.src = s2.y; e1.w = w2.y;
        g_csr[g_rs[d2.y] + r2.y] = e1;
    }
}

// ---------------------------------------------------------------------------
// GEMM1: h1h = dinv * (x @ W1)  (fp16 out). W column in registers.
__global__ void k_gemm1(const float* __restrict__ x, const float* __restrict__ W1) {
    __shared__ float4 xs[16][16];          // 16 rows x 64 floats
    int tx = threadIdx.x & 63;
    int ty = threadIdx.x >> 6;

    float4 w4[16];
    #pragma unroll
    for (int k4 = 0; k4 < 16; ++k4) {
        w4[k4].x = W1[(4 * k4 + 0) * 64 + tx];
        w4[k4].y = W1[(4 * k4 + 1) * 64 + tx];
        w4[k4].z = W1[(4 * k4 + 2) * 64 + tx];
        w4[k4].w = W1[(4 * k4 + 3) * 64 + tx];
    }

    int base = blockIdx.x * 64;
    for (int t = 0; t < 4; ++t) {
        int row0 = base + t * 16;
        __syncthreads();
        {
            int r = threadIdx.x >> 4, c = threadIdx.x & 15;
            if (row0 + r < N_NODES)
                xs[r][c] = ((const float4*)(x + (size_t)(row0 + r) * 64))[c];
        }
        __syncthreads();
        float acc[4] = {0.f, 0.f, 0.f, 0.f};
        #pragma unroll
        for (int k4 = 0; k4 < 16; ++k4) {
            float4 wv = w4[k4];
            #pragma unroll
            for (int r = 0; r < 4; ++r) {
                float4 xv = xs[ty * 4 + r][k4];
                acc[r] += xv.x * wv.x + xv.y * wv.y + xv.z * wv.z + xv.w * wv.w;
            }
        }
        #pragma unroll
        for (int r = 0; r < 4; ++r) {
            int row = row0 + ty * 4 + r;
            if (row < N_NODES)
                g_h1h[(size_t)row * 64 + tx] =
                    __float2half_rn(g_deg[row] * acc[r]);
        }
    }
}

// Aggregation layer 1: one warp per dst; unroll x8 for L2 MLP.
// o1 = relu( di*sum(ew_e*h1h[src_e]) + di*h1h[dst] + b1 )
__global__ void k_agg1(const float* __restrict__ b1) {
    int w = (blockIdx.x * blockDim.x + threadIdx.x) >> 5;
    int lane = threadIdx.x & 31;
    if (w >= N_NODES) return;
    int beg = g_rs[w];
    int n   = g_cnt[w];
    const __half2* h1v = (const __half2*)g_h1h;

    float a0 = 0.f, a1 = 0.f;
    int i = 0;
    for (; i + 7 < n; i += 8) {
        EdgeRec e0 = g_csr[beg + i + 0];
        EdgeRec e1 = g_csr[beg + i + 1];
        EdgeRec e2 = g_csr[beg + i + 2];
        EdgeRec e3 = g_csr[beg + i + 3];
        EdgeRec e4 = g_csr[beg + i + 4];
        EdgeRec e5 = g_csr[beg + i + 5];
        EdgeRec e6 = g_csr[beg + i + 6];
        EdgeRec e7 = g_csr[beg + i + 7];
        float2 f0 = __half22float2(__ldg(h1v + (size_t)e0.src * 32 + lane));
        float2 f1 = __half22float2(__ldg(h1v + (size_t)e1.src * 32 + lane));
        float2 f2 = __half22float2(__ldg(h1v + (size_t)e2.src * 32 + lane));
        float2 f3 = __half22float2(__ldg(h1v + (size_t)e3.src * 32 + lane));
        float2 f4 = __half22float2(__ldg(h1v + (size_t)e4.src * 32 + lane));
        float2 f5 = __half22float2(__ldg(h1v + (size_t)e5.src * 32 + lane));
        float2 f6 = __half22float2(__ldg(h1v + (size_t)e6.src * 32 + lane));
        float2 f7 = __half22float2(__ldg(h1v + (size_t)e7.src * 32 + lane));
        a0 += e0.w * f0.x + e1.w * f1.x + e2.w * f2.x + e3.w * f3.x
            + e4.w * f4.x + e5.w * f5.x + e6.w * f6.x + e7.w * f7.x;
        a1 += e0.w * f0.y + e1.w * f1.y + e2.w * f2.y + e3.w * f3.y
            + e4.w * f4.y + e5.w * f5.y + e6.w * f6.y + e7.w * f7.y;
    }
    for (; i < n; ++i) {
        EdgeRec er = g_csr[beg + i];
        float2 f = __half22float2(__ldg(h1v + (size_t)er.src * 32 + lane));
        a0 += er.w * f.x;
        a1 += er.w * f.y;
    }
    float di = g_deg[w];
    float2 hs = __half22float2(h1v[(size_t)w * 32 + lane]);  // dinv-scaled
    float2 bb = ((const float2*)b1)[lane];
    a0 = di * a0 + di * hs.x + bb.x;
    a1 = di * a1 + di * hs.y + bb.y;
    ((float2*)g_o1)[(size_t)w * 32 + lane] =
        make_float2(fmaxf(a0, 0.f), fmaxf(a1, 0.f));
}

// GEMM2: h2h = dinv * (o1 @ W2)  (fp16 out).
__global__ void k_gemm2(const float* __restrict__ W2) {
    __shared__ float4 xs[32][16];          // 32 rows x 64 floats
    int tx = threadIdx.x & 31;
    int ty = threadIdx.x >> 5;

    float4 w4[16];
    #pragma unroll
    for (int k4 = 0; k4 < 16; ++k4) {
        w4[k4].x = W2[(4 * k4 + 0) * 32 + tx];
        w4[k4].y = W2[(4 * k4 + 1) * 32 + tx];
        w4[k4].z = W2[(4 * k4 + 2) * 32 + tx];
        w4[k4].w = W2[(4 * k4 + 3) * 32 + tx];
    }

    int base = blockIdx.x * 128;
    for (int t = 0; t < 4; ++t) {
        int row0 = base + t * 32;
        __syncthreads();
        {
            int idx = threadIdx.x;
            #pragma unroll
            for (int j = 0; j < 2; ++j, idx += 256) {
                int r = idx >> 4, c = idx & 15;
                if (row0 + r < N_NODES)
                    xs[r][c] = ((const float4*)(g_o1 + (size_t)(row0 + r) * 64))[c];
            }
        }
        __syncthreads();
        float acc[4] = {0.f, 0.f, 0.f, 0.f};
        #pragma unroll
        for (int k4 = 0; k4 < 16; ++k4) {
            float4 wv = w4[k4];
            #pragma unroll
            for (int r = 0; r < 4; ++r) {
                float4 xv = xs[ty * 4 + r][k4];
                acc[r] += xv.x * wv.x + xv.y * wv.y + xv.z * wv.z + xv.w * wv.w;
            }
        }
        #pragma unroll
        for (int r = 0; r < 4; ++r) {
            int row = row0 + ty * 4 + r;
            if (row < N_NODES)
                g_h2h[(size_t)row * 32 + tx] =
                    __float2half_rn(g_deg[row] * acc[r]);
        }
    }
}

// Aggregation layer 2: warp per dst; half-warps interleave edges, unroll x4.
__global__ void k_agg2(const float* __restrict__ b2, float* __restrict__ out) {
    int w = (blockIdx.x * blockDim.x + threadIdx.x) >> 5;
    int lane = threadIdx.x & 31;
    if (w >= N_NODES) return;
    int half = lane >> 4;      // 0 or 1
    int c2   = lane & 15;      // half2 index within node
    int beg = g_rs[w];
    int n   = g_cnt[w];
    const __half2* h2v = (const __half2*)g_h2h;

    float a0 = 0.f, a1 = 0.f;
    int i = half;
    for (; i + 6 < n; i += 8) {       // this half handles i, i+2, i+4, i+6
        EdgeRec ea = g_csr[beg + i];
        EdgeRec eb = g_csr[beg + i + 2];
        EdgeRec ec = g_csr[beg + i + 4];
        EdgeRec ed = g_csr[beg + i + 6];
        float2 fa = __half22float2(__ldg(h2v + (size_t)ea.src * 16 + c2));
        float2 fb = __half22float2(__ldg(h2v + (size_t)eb.src * 16 + c2));
        float2 fc = __half22float2(__ldg(h2v + (size_t)ec.src * 16 + c2));
        float2 fd = __half22float2(__ldg(h2v + (size_t)ed.src * 16 + c2));
        a0 += ea.w * fa.x + eb.w * fb.x + ec.w * fc.x + ed.w * fd.x;
        a1 += ea.w * fa.y + eb.w * fb.y + ec.w * fc.y + ed.w * fd.y;
    }
    for (; i < n; i += 2) {
        EdgeRec er = g_csr[beg + i];
        float2 f = __half22float2(__ldg(h2v + (size_t)er.src * 16 + c2));
        a0 += er.w * f.x;
        a1 += er.w * f.y;
    }
    a0 += __shfl_xor_sync(0xffffffffu, a0, 16);
    a1 += __shfl_xor_sync(0xffffffffu, a1, 16);

    if (half == 0) {
        float di = g_deg[w];
        float2 hs = __half22float2(h2v[(size_t)w * 16 + c2]);   // dinv-scaled
        float2 bb = ((const float2*)b2)[c2];
        float o0  = di * a0 + di * hs.x + bb.x;
        float o1v = di * a1 + di * hs.y + bb.y;
        ((float2*)out)[(size_t)w * 16 + c2] = make_float2(o0, o1v);
    }
}

// ---------------------------------------------------------------------------
extern "C" void kernel_launch(void* const* d_in, const int* in_sizes, int n_in,
                              void* d_out, int out_size) {
    const float* x  = (const float*)d_in[0];
    const int*   ei = (const int*)d_in[1];
    const float* ew = (const float*)d_in[2];
    const float* W1 = (const float*)d_in[3];
    const float* b1 = (const float*)d_in[4];
    const float* W2 = (const float*)d_in[5];
    const float* b2 = (const float*)d_in[6];
    float* out = (float*)d_out;

    k_init <<<(N_NODES + 255) / 256, 256>>>();
    k_deg  <<<(N_EDGES / 2 + 255) / 256, 256>>>(ei, ew);
    k_scan <<<N_SCAN_BLOCKS, SCAN_BLK>>>();
    k_fill <<<(N_EDGES / 2 + 255) / 256, 256>>>(ei, ew);

    k_gemm1<<<(N_NODES + 63) / 64, 256>>>(x, W1);
    k_agg1 <<<(N_NODES * 32 + 255) / 256, 256>>>(b1);
    k_gemm2<<<(N_NODES + 127) / 128, 256>>>(W2);
    k_agg2 <<<(N_NODES * 32 + 255) / 256, 256>>>(b2, out);
}